// round 15
// baseline (speedup 1.0000x reference)
#include <cuda_runtime.h>
#include <cuda_fp16.h>
#include <cstdint>

// Problem dims (fixed)
#define BB 4
#define TT 4096
#define EE 1024
#define HH 64
#define BT (BB * TT)          // 16384 rows
#define SCALE 0.03125f        // E^-0.5

// Scratch (device globals)
__device__ __half g_Qh[BT * HH];    // Q in fp16 (written by qkv epilogue)
__device__ float g_M[BB * HH * HH];
__device__ __half g_WT[192 * EE];   // [n][k]; n: q 0-63, k 64-127, v 128-191

// ---------------------------------------------------------------------------
// PTX helpers (baseline PTX, valid under compute_103)
// ---------------------------------------------------------------------------
#define MMA_FP16(c, a, b)                                                     \
    asm volatile(                                                             \
        "mma.sync.aligned.m16n8k16.row.col.f32.f16.f16.f32 "                  \
        "{%0,%1,%2,%3}, {%4,%5,%6,%7}, {%8,%9}, {%0,%1,%2,%3};\n"             \
        : "+f"(c[0]), "+f"(c[1]), "+f"(c[2]), "+f"(c[3])                      \
        : "r"(a[0]), "r"(a[1]), "r"(a[2]), "r"(a[3]), "r"(b[0]), "r"(b[1]))

#define LDSM4(r0, r1, r2, r3, addr)                                           \
    asm volatile("ldmatrix.sync.aligned.m8n8.x4.shared.b16 {%0,%1,%2,%3}, [%4];" \
        : "=r"(r0), "=r"(r1), "=r"(r2), "=r"(r3) : "r"(addr))

#define CP_ASYNC16(dst, src) \
    asm volatile("cp.async.cg.shared.global [%0], [%1], 16;" :: "r"(dst), "l"(src))
#define CP_COMMIT() asm volatile("cp.async.commit_group;")
#define CP_WAIT0()  asm volatile("cp.async.wait_group 0;")

__device__ __forceinline__ uint32_t smem_u32(const void* p) {
    uint32_t a;
    asm("{ .reg .u64 t; cvta.to.shared.u64 t, %1; cvt.u32.u64 %0, t; }" : "=r"(a) : "l"(p));
    return a;
}

__device__ __forceinline__ uint32_t pack_h2(float a, float b) {
    __half2 p = __floats2half2_rn(a, b);
    return *(uint32_t*)&p;
}

// ---------------------------------------------------------------------------
// Prep: blocks 0..191: 16k x 64n transpose tiles of Wq|Wk|Wv -> fp16
// g_WT[n][k]. Blocks 192..207: zero g_M via float4.
// ---------------------------------------------------------------------------
__global__ __launch_bounds__(256) void prep_kernel(
    const float* __restrict__ Wq,
    const float* __restrict__ Wk,
    const float* __restrict__ Wv)
{
    const int t = threadIdx.x;
    const int bx = blockIdx.x;
    if (bx >= 192) {
        int i = (bx - 192) * 256 + t;
        ((float4*)g_M)[i] = make_float4(0.f, 0.f, 0.f, 0.f);
        return;
    }
    __shared__ float Ws[16][65];
    const int m  = bx >> 6;              // 0=Wq, 1=Wk, 2=Wv
    const int k0 = (bx & 63) * 16;
    const float* W = (m == 0) ? Wq : (m == 1) ? Wk : Wv;

#pragma unroll
    for (int l = 0; l < 4; l++) {
        int f = t + l * 256;
        int row = f >> 6;                // k-local 0..15
        int col = f & 63;                // n
        Ws[row][col] = W[(size_t)(k0 + row) * HH + col];
    }
    __syncthreads();
#pragma unroll
    for (int l = 0; l < 4; l++) {
        int f = t + l * 256;
        int n  = f >> 4;
        int kk = f & 15;
        g_WT[(size_t)(m * 64 + n) * EE + k0 + kk] = __float2half_rn(Ws[kk][n]);
    }
}

// ---------------------------------------------------------------------------
// Fused QKV + K^T V: block = 64 rows x 192 cols, single fp16 pass, BK=32,
// 2-stage cp.async pipeline (proven R12 shape). Q stored as fp16 -> g_Qh;
// K,V staged + K^T V outer product atomicAdd into g_M.
// grid = 256, 8 warps (2M x 4N), warp tile 32x48.
// Smem/buffer (20480B): Xh 64x80B @0, Wh 192x80B @5120. 2 bufs = 40960.
// Epilogue reuse: Ks[64][68] @0 + Vs[64][68] @17408 = 34816 B.
// ---------------------------------------------------------------------------
#define BUFS 20480
#define QKV_SMEM (2 * BUFS)

__global__ __launch_bounds__(256) void qkv_mma_kernel(
    const float* __restrict__ X,
    const float* __restrict__ bq,
    const float* __restrict__ bkk,
    const float* __restrict__ bv)
{
    extern __shared__ __align__(16) char sm[];
    const uint32_t sb = smem_u32(sm);
    const int t    = threadIdx.x;
    const int warp = t >> 5;
    const int lane = t & 31;
    const int g    = lane >> 2;
    const int tig  = lane & 3;
    const int wm   = warp >> 2;      // 0..1 -> m offset 32*wm
    const int wn   = warp & 3;       // 0..3 -> n offset 48*wn
    const int m0   = blockIdx.x * 64;
    const int batch = m0 >> 12;

    const float4* X4 = (const float4*)X;

    float c[2][6][4];
#pragma unroll
    for (int mt = 0; mt < 2; mt++)
#pragma unroll
        for (int nt = 0; nt < 6; nt++)
#pragma unroll
            for (int j = 0; j < 4; j++) c[mt][nt][j] = 0.f;

    float4 xr[2];
    const int xrow = t >> 2;         // 0..63
    const int xc4  = (t & 3) * 2;

    auto ldgX = [&](int k0) {
#pragma unroll
        for (int j = 0; j < 2; j++)
            xr[j] = X4[(size_t)(m0 + xrow) * (EE / 4) + (k0 >> 2) + xc4 + j];
    };
    auto stX = [&](int buf) {
        char* xh = sm + buf * BUFS;
#pragma unroll
        for (int j = 0; j < 2; j++) {
            uint32_t p0 = pack_h2(xr[j].x, xr[j].y);
            uint32_t p1 = pack_h2(xr[j].z, xr[j].w);
            int off = xrow * 80 + (xc4 + j) * 8;
            *(uint2*)(xh + off) = make_uint2(p0, p1);
        }
    };
    auto cpW = [&](int k0, int buf) {
        uint32_t wbase = sb + buf * BUFS + 5120;
#pragma unroll
        for (int j = 0; j < 3; j++) {
            int cc = t + j * 256;          // 0..767
            int row = cc >> 2;             // 0..191
            int q = cc & 3;
            const __half* src = g_WT + (size_t)row * EE + k0 + q * 8;
            uint32_t dst = wbase + row * 80 + q * 16;
            CP_ASYNC16(dst, src);
        }
    };
    auto domma = [&](int buf) {
        uint32_t xh = sb + buf * BUFS;
#pragma unroll
        for (int ks = 0; ks < 2; ks++) {
            const int kboff = ks * 32;
            uint32_t a[2][4], bh[6][2];
#pragma unroll
            for (int mt = 0; mt < 2; mt++) {
                uint32_t addr = xh + (uint32_t)((wm * 32 + mt * 16 + (lane & 15)) * 80
                                                + kboff + (lane >> 4) * 16);
                LDSM4(a[mt][0], a[mt][1], a[mt][2], a[mt][3], addr);
            }
#pragma unroll
            for (int nb = 0; nb < 3; nb++) {
                uint32_t addr = xh + 5120 + (uint32_t)((wn * 48 + nb * 16 + (lane & 15)) * 80
                                                       + kboff + (lane >> 4) * 16);
                uint32_t r0, r1, r2, r3;
                LDSM4(r0, r1, r2, r3, addr);
                bh[nb * 2][0] = r0; bh[nb * 2][1] = r2;
                bh[nb * 2 + 1][0] = r1; bh[nb * 2 + 1][1] = r3;
            }
#pragma unroll
            for (int mt = 0; mt < 2; mt++)
#pragma unroll
                for (int nt = 0; nt < 6; nt++)
                    MMA_FP16(c[mt][nt], a[mt], bh[nt]);
        }
    };

    // ---- 2-stage pipelined mainloop: 32 tiles of BK=32 ----
    ldgX(0);
    cpW(0, 0);
    CP_COMMIT();
    stX(0);
    for (int i = 0; i < 32; i++) {
        int buf = i & 1;
        CP_WAIT0();
        __syncthreads();
        if (i < 31) {
            ldgX((i + 1) * 32);
            cpW((i + 1) * 32, buf ^ 1);
            CP_COMMIT();
        }
        domma(buf);
        if (i < 31) stX(buf ^ 1);
    }
    __syncthreads();   // smem reusable for K/V staging

    // ---- epilogue: Q -> g_Qh (fp16); K,V -> smem; K^T V -> atomicAdd g_M ----
    float* Ks = (float*)sm;               // [64][68]
    float* Vs = (float*)(sm + 17408);     // [64][68]
#pragma unroll
    for (int mt = 0; mt < 2; mt++) {
        int r = wm * 32 + mt * 16 + g;
#pragma unroll
        for (int nt = 0; nt < 6; nt++) {
            int nbase = wn * 48 + nt * 8;
            int which = nbase >> 6;              // 0=Q, 1=K, 2=V
            int nc    = (nbase & 63) + 2 * tig;
            if (which == 0) {
                float b0v = bq[nc];
                float b1v = bq[nc + 1];
                uint32_t p0 = pack_h2(c[mt][nt][0] + b0v, c[mt][nt][1] + b1v);
                uint32_t p1 = pack_h2(c[mt][nt][2] + b0v, c[mt][nt][3] + b1v);
                *(uint32_t*)&g_Qh[(size_t)(m0 + r) * HH + nc] = p0;
                *(uint32_t*)&g_Qh[(size_t)(m0 + r + 8) * HH + nc] = p1;
            } else {
                const float* bias = (which == 1) ? bkk : bv;
                float* S = (which == 1) ? Ks : Vs;
                float b0v = bias[nc];
                float b1v = bias[nc + 1];
                S[r * 68 + nc]           = c[mt][nt][0] + b0v;
                S[r * 68 + nc + 1]       = c[mt][nt][1] + b1v;
                S[(r + 8) * 68 + nc]     = c[mt][nt][2] + b0v;
                S[(r + 8) * 68 + nc + 1] = c[mt][nt][3] + b1v;
            }
        }
    }
    __syncthreads();

    {
        const int i0 = (t >> 4) * 4;
        const int j0 = (t & 15) * 4;
        float acc[4][4];
#pragma unroll
        for (int i = 0; i < 4; i++)
#pragma unroll
            for (int j = 0; j < 4; j++) acc[i][j] = 0.f;
#pragma unroll 8
        for (int s = 0; s < 64; s++) {
            float4 kk = *(const float4*)&Ks[s * 68 + i0];
            float4 vv = *(const float4*)&Vs[s * 68 + j0];
            float a[4] = {kk.x, kk.y, kk.z, kk.w};
            float b2[4] = {vv.x, vv.y, vv.z, vv.w};
#pragma unroll
            for (int i = 0; i < 4; i++)
#pragma unroll
                for (int j = 0; j < 4; j++)
                    acc[i][j] += a[i] * b2[j];
        }
        float* Mb = g_M + (size_t)batch * HH * HH;
#pragma unroll
        for (int i = 0; i < 4; i++)
#pragma unroll
            for (int j = 0; j < 4; j++)
                atomicAdd(&Mb[(i0 + i) * HH + j0 + j], acc[i][j]);
    }
}

// ---------------------------------------------------------------------------
// out = SCALE * (Qh @ M), fp16 MMA: Q fp16 (as stored), M split hi+lo fp16
// (2-pass -> M contributes no rounding). Block = 64 rows x 64 cols, grid 256.
// 8 warps (2M x 4N), warp tile 32x16. K=64 resident (4 ks steps).
// ---------------------------------------------------------------------------
__global__ __launch_bounds__(256) void out_mma_kernel(float* __restrict__ out)
{
    __shared__ __half Qs[64][72];        // stride 144B, ldsm conflict-free
    __shared__ __half Mh[64][72];        // [n][k]
    __shared__ __half Ml[64][72];
    __shared__ float  Ms[64][68];        // fp32 staging, 16B-aligned rows

    const int t    = threadIdx.x;
    const int warp = t >> 5;
    const int lane = t & 31;
    const int g    = lane >> 2;
    const int tig  = lane & 3;
    const int wm   = warp >> 2;          // 0..1 -> m offset 32*wm
    const int wn   = warp & 3;           // 0..3 -> n offset 16*wn
    const int row0 = blockIdx.x * 64;
    const int batch = row0 >> 12;

    // cp.async Q tile: 64 rows x 128B = 512 x 16B chunks, 2/thread
#pragma unroll
    for (int l = 0; l < 2; l++) {
        int f = t + l * 256;
        int row = f >> 3;
        int q = f & 7;
        const __half* src = g_Qh + (size_t)(row0 + row) * HH + q * 8;
        CP_ASYNC16(smem_u32(&Qs[row][q * 8]), src);
    }
    // cp.async M (fp32): 4096 floats = 1024 x 16B chunks, 4/thread
#pragma unroll
    for (int l = 0; l < 4; l++) {
        int f = t + l * 256;
        int row = f >> 4;
        int q = f & 15;
        const float* src = g_M + (size_t)batch * HH * HH + row * 64 + q * 4;
        CP_ASYNC16(smem_u32(&Ms[row][q * 4]), src);
    }
    CP_COMMIT();
    CP_WAIT0();
    __syncthreads();

    // convert + transpose M -> Mh/Ml [n][k], 16 elems/thread
#pragma unroll
    for (int l = 0; l < 16; l++) {
        int f = t + l * 256;             // 0..4095
        int n = f >> 6;                  // 0..63
        int k = f & 63;
        float v = Ms[k][n];
        __half hi = __float2half_rn(v);
        __half lo = __float2half_rn(v - __half2float(hi));
        Mh[n][k] = hi;
        Ml[n][k] = lo;
    }
    __syncthreads();

    float c[2][2][4];
#pragma unroll
    for (int mt = 0; mt < 2; mt++)
#pragma unroll
        for (int nt = 0; nt < 2; nt++)
#pragma unroll
            for (int j = 0; j < 4; j++) c[mt][nt][j] = 0.f;

#pragma unroll
    for (int ks = 0; ks < 4; ks++) {
        const int kboff = ks * 32;       // bytes
        uint32_t a[2][4];
#pragma unroll
        for (int mt = 0; mt < 2; mt++) {
            uint32_t addr = smem_u32(&Qs[wm * 32 + mt * 16 + (lane & 15)][0])
                          + kboff + (lane >> 4) * 16;
            LDSM4(a[mt][0], a[mt][1], a[mt][2], a[mt][3], addr);
        }
        uint32_t bh[2][2], bl[2][2];
        {
            uint32_t addr = smem_u32(&Mh[wn * 16 + (lane & 15)][0])
                          + kboff + (lane >> 4) * 16;
            uint32_t r0, r1, r2, r3;
            LDSM4(r0, r1, r2, r3, addr);
            bh[0][0] = r0; bh[0][1] = r2;
            bh[1][0] = r1; bh[1][1] = r3;
        }
        {
            uint32_t addr = smem_u32(&Ml[wn * 16 + (lane & 15)][0])
                          + kboff + (lane >> 4) * 16;
            uint32_t r0, r1, r2, r3;
            LDSM4(r0, r1, r2, r3, addr);
            bl[0][0] = r0; bl[0][1] = r2;
            bl[1][0] = r1; bl[1][1] = r3;
        }
#pragma unroll
        for (int mt = 0; mt < 2; mt++)
#pragma unroll
            for (int nt = 0; nt < 2; nt++) {
                MMA_FP16(c[mt][nt], a[mt], bh[nt]);
                MMA_FP16(c[mt][nt], a[mt], bl[nt]);
            }
    }

    // epilogue: scale + store fp32
#pragma unroll
    for (int mt = 0; mt < 2; mt++) {
        int r = row0 + wm * 32 + mt * 16 + g;
#pragma unroll
        for (int nt = 0; nt < 2; nt++) {
            int n = wn * 16 + nt * 8 + 2 * tig;
            float2 o0 = {c[mt][nt][0] * SCALE, c[mt][nt][1] * SCALE};
            float2 o1 = {c[mt][nt][2] * SCALE, c[mt][nt][3] * SCALE};
            *(float2*)&out[(size_t)r * HH + n] = o0;
            *(float2*)&out[(size_t)(r + 8) * HH + n] = o1;
        }
    }
}

// ---------------------------------------------------------------------------
// Launch
// ---------------------------------------------------------------------------
extern "C" void kernel_launch(void* const* d_in, const int* in_sizes, int n_in,
                              void* d_out, int out_size)
{
    const float* idx = (const float*)d_in[0];
    const float* Wq  = (const float*)d_in[1];
    const float* bq  = (const float*)d_in[2];
    const float* Wk  = (const float*)d_in[3];
    const float* bk  = (const float*)d_in[4];
    const float* Wv  = (const float*)d_in[5];
    const float* bv  = (const float*)d_in[6];
    float* out = (float*)d_out;

    prep_kernel<<<208, 256>>>(Wq, Wk, Wv);

    qkv_mma_kernel<<<BT / 64, 256, QKV_SMEM>>>(idx, bq, bk, bv);

    out_mma_kernel<<<BT / 64, 256>>>(out);
}

// round 16
// speedup vs baseline: 1.3656x; 1.3656x over previous
#include <cuda_runtime.h>
#include <cuda_fp16.h>
#include <cstdint>

// Problem dims (fixed)
#define BB 4
#define TT 4096
#define EE 1024
#define HH 64
#define BT (BB * TT)          // 16384 rows
#define SCALE 0.03125f        // E^-0.5

// Scratch (device globals)
__device__ float g_Q[BT * HH];
__device__ float g_M[BB * HH * HH];
__device__ __half g_WT[192 * EE];   // [n][k]; n: q 0-63, k 64-127, v 128-191

// ---------------------------------------------------------------------------
// PTX helpers (baseline PTX, valid under compute_103)
// ---------------------------------------------------------------------------
#define MMA_FP16(c, a, b)                                                     \
    asm volatile(                                                             \
        "mma.sync.aligned.m16n8k16.row.col.f32.f16.f16.f32 "                  \
        "{%0,%1,%2,%3}, {%4,%5,%6,%7}, {%8,%9}, {%0,%1,%2,%3};\n"             \
        : "+f"(c[0]), "+f"(c[1]), "+f"(c[2]), "+f"(c[3])                      \
        : "r"(a[0]), "r"(a[1]), "r"(a[2]), "r"(a[3]), "r"(b[0]), "r"(b[1]))

#define LDSM4(r0, r1, r2, r3, addr)                                           \
    asm volatile("ldmatrix.sync.aligned.m8n8.x4.shared.b16 {%0,%1,%2,%3}, [%4];" \
        : "=r"(r0), "=r"(r1), "=r"(r2), "=r"(r3) : "r"(addr))

#define CP_ASYNC16(dst, src) \
    asm volatile("cp.async.cg.shared.global [%0], [%1], 16;" :: "r"(dst), "l"(src))
#define CP_COMMIT() asm volatile("cp.async.commit_group;")
#define CP_WAIT0()  asm volatile("cp.async.wait_group 0;")

__device__ __forceinline__ uint32_t smem_u32(const void* p) {
    uint32_t a;
    asm("{ .reg .u64 t; cvta.to.shared.u64 t, %1; cvt.u32.u64 %0, t; }" : "=r"(a) : "l"(p));
    return a;
}

// ---------------------------------------------------------------------------
// Prep (R14 version, 4.4us): blocks 0..191: 16k x 64n transpose tiles of
// Wq|Wk|Wv -> fp16 g_WT[n][k]. Blocks 192..207: zero g_M via float4.
// ---------------------------------------------------------------------------
__global__ __launch_bounds__(256) void prep_kernel(
    const float* __restrict__ Wq,
    const float* __restrict__ Wk,
    const float* __restrict__ Wv)
{
    const int t = threadIdx.x;
    const int bx = blockIdx.x;
    if (bx >= 192) {
        int i = (bx - 192) * 256 + t;
        ((float4*)g_M)[i] = make_float4(0.f, 0.f, 0.f, 0.f);
        return;
    }
    __shared__ float Ws[16][65];
    const int m  = bx >> 6;              // 0=Wq, 1=Wk, 2=Wv
    const int k0 = (bx & 63) * 16;
    const float* W = (m == 0) ? Wq : (m == 1) ? Wk : Wv;

#pragma unroll
    for (int l = 0; l < 4; l++) {
        int f = t + l * 256;
        int row = f >> 6;                // k-local 0..15
        int col = f & 63;                // n
        Ws[row][col] = W[(size_t)(k0 + row) * HH + col];
    }
    __syncthreads();
#pragma unroll
    for (int l = 0; l < 4; l++) {
        int f = t + l * 256;
        int n  = f >> 4;
        int kk = f & 15;
        g_WT[(size_t)(m * 64 + n) * EE + k0 + kk] = __float2half_rn(Ws[kk][n]);
    }
}

// ---------------------------------------------------------------------------
// Fused QKV + K^T V (R12 exact): block = 64 rows x 192 cols, single fp16
// pass, BK=32, 2-stage cp.async pipeline. Q -> g_Q fp32; K,V staged + K^T V
// outer product atomicAdd into g_M. grid = 256, 8 warps (2M x 4N), 32x48.
// Smem/buffer (20480B): Xh 64x80B @0, Wh 192x80B @5120. 2 bufs = 40960.
// Epilogue reuse: Ks[64][68] @0 + Vs[64][68] @17408 = 34816 B.
// ---------------------------------------------------------------------------
#define BUFS 20480
#define QKV_SMEM (2 * BUFS)

__global__ __launch_bounds__(256) void qkv_mma_kernel(
    const float* __restrict__ X,
    const float* __restrict__ bq,
    const float* __restrict__ bkk,
    const float* __restrict__ bv)
{
    extern __shared__ __align__(16) char sm[];
    const uint32_t sb = smem_u32(sm);
    const int t    = threadIdx.x;
    const int warp = t >> 5;
    const int lane = t & 31;
    const int g    = lane >> 2;
    const int tig  = lane & 3;
    const int wm   = warp >> 2;      // 0..1 -> m offset 32*wm
    const int wn   = warp & 3;       // 0..3 -> n offset 48*wn
    const int m0   = blockIdx.x * 64;
    const int batch = m0 >> 12;

    const float4* X4 = (const float4*)X;

    float c[2][6][4];
#pragma unroll
    for (int mt = 0; mt < 2; mt++)
#pragma unroll
        for (int nt = 0; nt < 6; nt++)
#pragma unroll
            for (int j = 0; j < 4; j++) c[mt][nt][j] = 0.f;

    float4 xr[2];
    const int xrow = t >> 2;         // 0..63
    const int xc4  = (t & 3) * 2;    // float4 chunks xc4, xc4+1

    auto ldgX = [&](int k0) {
#pragma unroll
        for (int j = 0; j < 2; j++)
            xr[j] = X4[(size_t)(m0 + xrow) * (EE / 4) + (k0 >> 2) + xc4 + j];
    };
    auto stX = [&](int buf) {
        char* xh = sm + buf * BUFS;
#pragma unroll
        for (int j = 0; j < 2; j++) {
            __half2 p0 = __floats2half2_rn(xr[j].x, xr[j].y);
            __half2 p1 = __floats2half2_rn(xr[j].z, xr[j].w);
            int off = xrow * 80 + (xc4 + j) * 8;
            *(uint2*)(xh + off) = make_uint2(*(uint32_t*)&p0, *(uint32_t*)&p1);
        }
    };
    // W tile: 192 rows x 32 cols fp16 = 768 x 16B, 3/thread
    auto cpW = [&](int k0, int buf) {
        uint32_t wbase = sb + buf * BUFS + 5120;
#pragma unroll
        for (int j = 0; j < 3; j++) {
            int cc = t + j * 256;          // 0..767
            int row = cc >> 2;             // 0..191
            int q = cc & 3;
            const __half* src = g_WT + (size_t)row * EE + k0 + q * 8;
            uint32_t dst = wbase + row * 80 + q * 16;
            CP_ASYNC16(dst, src);
        }
    };
    auto domma = [&](int buf) {
        uint32_t xh = sb + buf * BUFS;
#pragma unroll
        for (int ks = 0; ks < 2; ks++) {
            const int kboff = ks * 32;
            uint32_t a[2][4], bh[6][2];
#pragma unroll
            for (int mt = 0; mt < 2; mt++) {
                uint32_t addr = xh + (uint32_t)((wm * 32 + mt * 16 + (lane & 15)) * 80
                                                + kboff + (lane >> 4) * 16);
                LDSM4(a[mt][0], a[mt][1], a[mt][2], a[mt][3], addr);
            }
#pragma unroll
            for (int nb = 0; nb < 3; nb++) {
                uint32_t addr = xh + 5120 + (uint32_t)((wn * 48 + nb * 16 + (lane & 15)) * 80
                                                       + kboff + (lane >> 4) * 16);
                uint32_t r0, r1, r2, r3;
                LDSM4(r0, r1, r2, r3, addr);
                bh[nb * 2][0] = r0; bh[nb * 2][1] = r2;
                bh[nb * 2 + 1][0] = r1; bh[nb * 2 + 1][1] = r3;
            }
#pragma unroll
            for (int mt = 0; mt < 2; mt++)
#pragma unroll
                for (int nt = 0; nt < 6; nt++)
                    MMA_FP16(c[mt][nt], a[mt], bh[nt]);
        }
    };

    // ---- 2-stage pipelined mainloop: 32 tiles of BK=32 ----
    ldgX(0);
    cpW(0, 0);
    CP_COMMIT();
    stX(0);
    for (int i = 0; i < 32; i++) {
        int buf = i & 1;
        CP_WAIT0();
        __syncthreads();
        if (i < 31) {
            ldgX((i + 1) * 32);
            cpW((i + 1) * 32, buf ^ 1);
            CP_COMMIT();
        }
        domma(buf);
        if (i < 31) stX(buf ^ 1);
    }
    __syncthreads();   // smem reusable for K/V staging

    // ---- epilogue: Q -> g_Q; K,V -> smem; K^T V -> atomicAdd g_M ----
    float* Ks = (float*)sm;               // [64][68]
    float* Vs = (float*)(sm + 17408);     // [64][68]
#pragma unroll
    for (int mt = 0; mt < 2; mt++) {
        int r = wm * 32 + mt * 16 + g;
#pragma unroll
        for (int nt = 0; nt < 6; nt++) {
            int nbase = wn * 48 + nt * 8;
            int which = nbase >> 6;              // 0=Q, 1=K, 2=V
            int nc    = (nbase & 63) + 2 * tig;
            if (which == 0) {
                float b0v = bq[nc];
                float b1v = bq[nc + 1];
                float2 o0 = {c[mt][nt][0] + b0v, c[mt][nt][1] + b1v};
                float2 o1 = {c[mt][nt][2] + b0v, c[mt][nt][3] + b1v};
                *(float2*)&g_Q[(size_t)(m0 + r) * HH + nc] = o0;
                *(float2*)&g_Q[(size_t)(m0 + r + 8) * HH + nc] = o1;
            } else {
                const float* bias = (which == 1) ? bkk : bv;
                float* S = (which == 1) ? Ks : Vs;
                float b0v = bias[nc];
                float b1v = bias[nc + 1];
                S[r * 68 + nc]           = c[mt][nt][0] + b0v;
                S[r * 68 + nc + 1]       = c[mt][nt][1] + b1v;
                S[(r + 8) * 68 + nc]     = c[mt][nt][2] + b0v;
                S[(r + 8) * 68 + nc + 1] = c[mt][nt][3] + b1v;
            }
        }
    }
    __syncthreads();

    {
        const int i0 = (t >> 4) * 4;
        const int j0 = (t & 15) * 4;
        float acc[4][4];
#pragma unroll
        for (int i = 0; i < 4; i++)
#pragma unroll
            for (int j = 0; j < 4; j++) acc[i][j] = 0.f;
#pragma unroll 8
        for (int s = 0; s < 64; s++) {
            float4 kk = *(const float4*)&Ks[s * 68 + i0];
            float4 vv = *(const float4*)&Vs[s * 68 + j0];
            float a[4] = {kk.x, kk.y, kk.z, kk.w};
            float b2[4] = {vv.x, vv.y, vv.z, vv.w};
#pragma unroll
            for (int i = 0; i < 4; i++)
#pragma unroll
                for (int j = 0; j < 4; j++)
                    acc[i][j] += a[i] * b2[j];
        }
        float* Mb = g_M + (size_t)batch * HH * HH;
#pragma unroll
        for (int i = 0; i < 4; i++)
#pragma unroll
            for (int j = 0; j < 4; j++)
                atomicAdd(&Mb[(i0 + i) * HH + j0 + j], acc[i][j]);
    }
}

// ---------------------------------------------------------------------------
// out[b] = SCALE * Q[b] @ M[b].  32 rows per block -> grid BT/32 = 512.
// ---------------------------------------------------------------------------
__global__ __launch_bounds__(256) void out_kernel(float* __restrict__ out)
{
    __shared__ float Ms[64][68];
    __shared__ float Qs[32][68];

    const int t    = threadIdx.x;
    const int tx   = t & 15;
    const int ty   = t >> 4;
    const int row0 = blockIdx.x * 32;
    const int b    = row0 / TT;

    const float4* Q4 = (const float4*)(g_Q + (size_t)row0 * HH);
    const float4* M4 = (const float4*)(g_M + (size_t)b * HH * HH);

#pragma unroll
    for (int l = 0; l < 2; l++) {
        int f   = t + l * 256;
        int row = f >> 4;
        int c4  = f & 15;
        *(float4*)&Qs[row][c4 * 4] = Q4[(size_t)row * 16 + c4];
    }
#pragma unroll
    for (int l = 0; l < 4; l++) {
        int f   = t + l * 256;
        int row = f >> 4;
        int c4  = f & 15;
        *(float4*)&Ms[row][c4 * 4] = M4[(size_t)row * 16 + c4];
    }
    __syncthreads();

    float acc[2][4];
#pragma unroll
    for (int i = 0; i < 2; i++)
#pragma unroll
        for (int j = 0; j < 4; j++) acc[i][j] = 0.f;

#pragma unroll 4
    for (int k0 = 0; k0 < 64; k0 += 4) {
        float4 q4[2];
#pragma unroll
        for (int i = 0; i < 2; i++)
            q4[i] = *(const float4*)&Qs[ty * 2 + i][k0];
#pragma unroll
        for (int kk = 0; kk < 4; kk++) {
            float4 m4 = *(const float4*)&Ms[k0 + kk][tx * 4];
            float m[4] = {m4.x, m4.y, m4.z, m4.w};
#pragma unroll
            for (int i = 0; i < 2; i++) {
                float qv = (kk == 0) ? q4[i].x : (kk == 1) ? q4[i].y
                         : (kk == 2) ? q4[i].z : q4[i].w;
#pragma unroll
                for (int j = 0; j < 4; j++)
                    acc[i][j] += qv * m[j];
            }
        }
    }

#pragma unroll
    for (int i = 0; i < 2; i++) {
        int r = row0 + ty * 2 + i;
        float4 o;
        o.x = acc[i][0] * SCALE;
        o.y = acc[i][1] * SCALE;
        o.z = acc[i][2] * SCALE;
        o.w = acc[i][3] * SCALE;
        *(float4*)&out[(size_t)r * HH + tx * 4] = o;
    }
}

// ---------------------------------------------------------------------------
// Launch
// ---------------------------------------------------------------------------
extern "C" void kernel_launch(void* const* d_in, const int* in_sizes, int n_in,
                              void* d_out, int out_size)
{
    const float* idx = (const float*)d_in[0];
    const float* Wq  = (const float*)d_in[1];
    const float* bq  = (const float*)d_in[2];
    const float* Wk  = (const float*)d_in[3];
    const float* bk  = (const float*)d_in[4];
    const float* Wv  = (const float*)d_in[5];
    const float* bv  = (const float*)d_in[6];
    float* out = (float*)d_out;

    prep_kernel<<<208, 256>>>(Wq, Wk, Wv);

    qkv_mma_kernel<<<BT / 64, 256, QKV_SMEM>>>(idx, bq, bk, bv);

    out_kernel<<<BT / 32, 256>>>(out);
}

// round 17
// speedup vs baseline: 1.3761x; 1.0077x over previous
#include <cuda_runtime.h>
#include <cuda_fp16.h>
#include <cstdint>
#include <cstring>

// Problem dims (fixed)
#define BB 4
#define TT 4096
#define EE 1024
#define HH 64
#define BT (BB * TT)          // 16384 rows
#define SCALE 0.03125f        // E^-0.5

// Scratch (device globals)
__device__ float g_Q[BT * HH];
__device__ float g_M[BB * HH * HH];
__device__ __half g_WT[192 * EE];   // [n][k]; n: q 0-63, k 64-127, v 128-191

// ---------------------------------------------------------------------------
// PTX helpers (baseline PTX; f32x2 is sm_100-family baseline, not 'a'-only)
// ---------------------------------------------------------------------------
#define MMA_FP16(c, a, b)                                                     \
    asm volatile(                                                             \
        "mma.sync.aligned.m16n8k16.row.col.f32.f16.f16.f32 "                  \
        "{%0,%1,%2,%3}, {%4,%5,%6,%7}, {%8,%9}, {%0,%1,%2,%3};\n"             \
        : "+f"(c[0]), "+f"(c[1]), "+f"(c[2]), "+f"(c[3])                      \
        : "r"(a[0]), "r"(a[1]), "r"(a[2]), "r"(a[3]), "r"(b[0]), "r"(b[1]))

#define LDSM4(r0, r1, r2, r3, addr)                                           \
    asm volatile("ldmatrix.sync.aligned.m8n8.x4.shared.b16 {%0,%1,%2,%3}, [%4];" \
        : "=r"(r0), "=r"(r1), "=r"(r2), "=r"(r3) : "r"(addr))

#define CP_ASYNC16(dst, src) \
    asm volatile("cp.async.cg.shared.global [%0], [%1], 16;" :: "r"(dst), "l"(src))
#define CP_COMMIT() asm volatile("cp.async.commit_group;")
#define CP_WAIT0()  asm volatile("cp.async.wait_group 0;")

// packed dual-FMA: d = a * b + d (two fp32 lanes)
#define FMA_F32X2(d, a, b) \
    asm volatile("fma.rn.f32x2 %0, %1, %2, %0;" : "+l"(d) : "l"(a), "l"(b))

__device__ __forceinline__ uint32_t smem_u32(const void* p) {
    uint32_t a;
    asm("{ .reg .u64 t; cvta.to.shared.u64 t, %1; cvt.u32.u64 %0, t; }" : "=r"(a) : "l"(p));
    return a;
}

__device__ __forceinline__ unsigned long long dup_f32(float v) {
    uint32_t b = __float_as_uint(v);
    return ((unsigned long long)b << 32) | b;
}

// ---------------------------------------------------------------------------
// Prep: blocks 0..191: 16k x 64n transpose tiles of Wq|Wk|Wv -> fp16
// g_WT[n][k]. First 16 blocks additionally zero g_M (4096 float4 total).
// ---------------------------------------------------------------------------
__global__ __launch_bounds__(256) void prep_kernel(
    const float* __restrict__ Wq,
    const float* __restrict__ Wk,
    const float* __restrict__ Wv)
{
    const int t = threadIdx.x;
    const int bx = blockIdx.x;

    if (bx < 16) {
        int i = bx * 256 + t;            // 0..4095
        ((float4*)g_M)[i] = make_float4(0.f, 0.f, 0.f, 0.f);
    }

    __shared__ float Ws[16][65];
    const int m  = bx >> 6;              // 0=Wq, 1=Wk, 2=Wv
    const int k0 = (bx & 63) * 16;
    const float* W = (m == 0) ? Wq : (m == 1) ? Wk : Wv;

#pragma unroll
    for (int l = 0; l < 4; l++) {
        int f = t + l * 256;
        int row = f >> 6;                // k-local 0..15
        int col = f & 63;                // n
        Ws[row][col] = W[(size_t)(k0 + row) * HH + col];
    }
    __syncthreads();
#pragma unroll
    for (int l = 0; l < 4; l++) {
        int f = t + l * 256;
        int n  = f >> 4;
        int kk = f & 15;
        g_WT[(size_t)(m * 64 + n) * EE + k0 + kk] = __float2half_rn(Ws[kk][n]);
    }
}

// ---------------------------------------------------------------------------
// Fused QKV + K^T V: block = 64 rows x 192 cols, single fp16 pass, BK=32,
// 2-stage cp.async pipeline. Q -> g_Q fp32; K,V staged + K^T V outer product
// (f32x2 packed FMA) atomicAdd into g_M. grid = 256, 8 warps (2M x 4N).
// Smem/buffer (20480B): Xh 64x80B @0, Wh 192x80B @5120. 2 bufs = 40960.
// Epilogue reuse: Ks[64][68] @0 + Vs[64][68] @17408 = 34816 B.
// ---------------------------------------------------------------------------
#define BUFS 20480
#define QKV_SMEM (2 * BUFS)

__global__ __launch_bounds__(256) void qkv_mma_kernel(
    const float* __restrict__ X,
    const float* __restrict__ bq,
    const float* __restrict__ bkk,
    const float* __restrict__ bv)
{
    extern __shared__ __align__(16) char sm[];
    const uint32_t sb = smem_u32(sm);
    const int t    = threadIdx.x;
    const int warp = t >> 5;
    const int lane = t & 31;
    const int g    = lane >> 2;
    const int tig  = lane & 3;
    const int wm   = warp >> 2;      // 0..1 -> m offset 32*wm
    const int wn   = warp & 3;       // 0..3 -> n offset 48*wn
    const int m0   = blockIdx.x * 64;
    const int batch = m0 >> 12;

    const float4* X4 = (const float4*)X;

    float c[2][6][4];
#pragma unroll
    for (int mt = 0; mt < 2; mt++)
#pragma unroll
        for (int nt = 0; nt < 6; nt++)
#pragma unroll
            for (int j = 0; j < 4; j++) c[mt][nt][j] = 0.f;

    float4 xr[2];
    const int xrow = t >> 2;         // 0..63
    const int xc4  = (t & 3) * 2;    // float4 chunks xc4, xc4+1

    auto ldgX = [&](int k0) {
#pragma unroll
        for (int j = 0; j < 2; j++)
            xr[j] = X4[(size_t)(m0 + xrow) * (EE / 4) + (k0 >> 2) + xc4 + j];
    };
    auto stX = [&](int buf) {
        char* xh = sm + buf * BUFS;
#pragma unroll
        for (int j = 0; j < 2; j++) {
            __half2 p0 = __floats2half2_rn(xr[j].x, xr[j].y);
            __half2 p1 = __floats2half2_rn(xr[j].z, xr[j].w);
            int off = xrow * 80 + (xc4 + j) * 8;
            *(uint2*)(xh + off) = make_uint2(*(uint32_t*)&p0, *(uint32_t*)&p1);
        }
    };
    // W tile: 192 rows x 32 cols fp16 = 768 x 16B, 3/thread
    auto cpW = [&](int k0, int buf) {
        uint32_t wbase = sb + buf * BUFS + 5120;
#pragma unroll
        for (int j = 0; j < 3; j++) {
            int cc = t + j * 256;          // 0..767
            int row = cc >> 2;             // 0..191
            int q = cc & 3;
            const __half* src = g_WT + (size_t)row * EE + k0 + q * 8;
            uint32_t dst = wbase + row * 80 + q * 16;
            CP_ASYNC16(dst, src);
        }
    };
    auto domma = [&](int buf) {
        uint32_t xh = sb + buf * BUFS;
#pragma unroll
        for (int ks = 0; ks < 2; ks++) {
            const int kboff = ks * 32;
            uint32_t a[2][4], bh[6][2];
#pragma unroll
            for (int mt = 0; mt < 2; mt++) {
                uint32_t addr = xh + (uint32_t)((wm * 32 + mt * 16 + (lane & 15)) * 80
                                                + kboff + (lane >> 4) * 16);
                LDSM4(a[mt][0], a[mt][1], a[mt][2], a[mt][3], addr);
            }
#pragma unroll
            for (int nb = 0; nb < 3; nb++) {
                uint32_t addr = xh + 5120 + (uint32_t)((wn * 48 + nb * 16 + (lane & 15)) * 80
                                                       + kboff + (lane >> 4) * 16);
                uint32_t r0, r1, r2, r3;
                LDSM4(r0, r1, r2, r3, addr);
                bh[nb * 2][0] = r0; bh[nb * 2][1] = r2;
                bh[nb * 2 + 1][0] = r1; bh[nb * 2 + 1][1] = r3;
            }
#pragma unroll
            for (int mt = 0; mt < 2; mt++)
#pragma unroll
                for (int nt = 0; nt < 6; nt++)
                    MMA_FP16(c[mt][nt], a[mt], bh[nt]);
        }
    };

    // ---- 2-stage pipelined mainloop: 32 tiles of BK=32 ----
    ldgX(0);
    cpW(0, 0);
    CP_COMMIT();
    stX(0);
    for (int i = 0; i < 32; i++) {
        int buf = i & 1;
        CP_WAIT0();
        __syncthreads();
        if (i < 31) {
            ldgX((i + 1) * 32);
            cpW((i + 1) * 32, buf ^ 1);
            CP_COMMIT();
        }
        domma(buf);
        if (i < 31) stX(buf ^ 1);
    }
    __syncthreads();   // smem reusable for K/V staging

    // ---- epilogue: Q -> g_Q; K,V -> smem; K^T V -> atomicAdd g_M ----
    float* Ks = (float*)sm;               // [64][68]
    float* Vs = (float*)(sm + 17408);     // [64][68]
#pragma unroll
    for (int mt = 0; mt < 2; mt++) {
        int r = wm * 32 + mt * 16 + g;
#pragma unroll
        for (int nt = 0; nt < 6; nt++) {
            int nbase = wn * 48 + nt * 8;
            int which = nbase >> 6;              // 0=Q, 1=K, 2=V
            int nc    = (nbase & 63) + 2 * tig;
            if (which == 0) {
                float b0v = bq[nc];
                float b1v = bq[nc + 1];
                float2 o0 = {c[mt][nt][0] + b0v, c[mt][nt][1] + b1v};
                float2 o1 = {c[mt][nt][2] + b0v, c[mt][nt][3] + b1v};
                *(float2*)&g_Q[(size_t)(m0 + r) * HH + nc] = o0;
                *(float2*)&g_Q[(size_t)(m0 + r + 8) * HH + nc] = o1;
            } else {
                const float* bias = (which == 1) ? bkk : bv;
                float* S = (which == 1) ? Ks : Vs;
                float b0v = bias[nc];
                float b1v = bias[nc + 1];
                S[r * 68 + nc]           = c[mt][nt][0] + b0v;
                S[r * 68 + nc + 1]       = c[mt][nt][1] + b1v;
                S[(r + 8) * 68 + nc]     = c[mt][nt][2] + b0v;
                S[(r + 8) * 68 + nc + 1] = c[mt][nt][3] + b1v;
            }
        }
    }
    __syncthreads();

    // 64-deep outer product with packed f32x2 FMA (same accumulation order)
    {
        const int i0 = (t >> 4) * 4;
        const int j0 = (t & 15) * 4;
        unsigned long long acc2[4][2];
#pragma unroll
        for (int i = 0; i < 4; i++)
#pragma unroll
            for (int jp = 0; jp < 2; jp++) acc2[i][jp] = 0ull;
#pragma unroll 8
        for (int s = 0; s < 64; s++) {
            float4 kk = *(const float4*)&Ks[s * 68 + i0];
            unsigned long long b0 = *(const unsigned long long*)&Vs[s * 68 + j0];
            unsigned long long b1 = *(const unsigned long long*)&Vs[s * 68 + j0 + 2];
            float a[4] = {kk.x, kk.y, kk.z, kk.w};
#pragma unroll
            for (int i = 0; i < 4; i++) {
                unsigned long long a2 = dup_f32(a[i]);
                FMA_F32X2(acc2[i][0], a2, b0);
                FMA_F32X2(acc2[i][1], a2, b1);
            }
        }
        float* Mb = g_M + (size_t)batch * HH * HH;
#pragma unroll
        for (int i = 0; i < 4; i++)
#pragma unroll
            for (int jp = 0; jp < 2; jp++) {
                float2 v;
                memcpy(&v, &acc2[i][jp], 8);
                atomicAdd(&Mb[(i0 + i) * HH + j0 + 2 * jp], v.x);
                atomicAdd(&Mb[(i0 + i) * HH + j0 + 2 * jp + 1], v.y);
            }
    }
}

// ---------------------------------------------------------------------------
// out[b] = SCALE * Q[b] @ M[b].  32 rows per block -> grid BT/32 = 512.
// Inner loop uses packed f32x2 FMA.
// ---------------------------------------------------------------------------
__global__ __launch_bounds__(256) void out_kernel(float* __restrict__ out)
{
    __shared__ float Ms[64][68];
    __shared__ float Qs[32][68];

    const int t    = threadIdx.x;
    const int tx   = t & 15;
    const int ty   = t >> 4;
    const int row0 = blockIdx.x * 32;
    const int b    = row0 / TT;

    const float4* Q4 = (const float4*)(g_Q + (size_t)row0 * HH);
    const float4* M4 = (const float4*)(g_M + (size_t)b * HH * HH);

#pragma unroll
    for (int l = 0; l < 2; l++) {
        int f   = t + l * 256;
        int row = f >> 4;
        int c4  = f & 15;
        *(float4*)&Qs[row][c4 * 4] = Q4[(size_t)row * 16 + c4];
    }
#pragma unroll
    for (int l = 0; l < 4; l++) {
        int f   = t + l * 256;
        int row = f >> 4;
        int c4  = f & 15;
        *(float4*)&Ms[row][c4 * 4] = M4[(size_t)row * 16 + c4];
    }
    __syncthreads();

    unsigned long long acc2[2][2];
#pragma unroll
    for (int i = 0; i < 2; i++)
#pragma unroll
        for (int jp = 0; jp < 2; jp++) acc2[i][jp] = 0ull;

#pragma unroll 4
    for (int k0 = 0; k0 < 64; k0 += 4) {
        float4 q4[2];
#pragma unroll
        for (int i = 0; i < 2; i++)
            q4[i] = *(const float4*)&Qs[ty * 2 + i][k0];
#pragma unroll
        for (int kk = 0; kk < 4; kk++) {
            unsigned long long m0 = *(const unsigned long long*)&Ms[k0 + kk][tx * 4];
            unsigned long long m1 = *(const unsigned long long*)&Ms[k0 + kk][tx * 4 + 2];
#pragma unroll
            for (int i = 0; i < 2; i++) {
                float qv = (kk == 0) ? q4[i].x : (kk == 1) ? q4[i].y
                         : (kk == 2) ? q4[i].z : q4[i].w;
                unsigned long long q2 = dup_f32(qv);
                FMA_F32X2(acc2[i][0], q2, m0);
                FMA_F32X2(acc2[i][1], q2, m1);
            }
        }
    }

#pragma unroll
    for (int i = 0; i < 2; i++) {
        int r = row0 + ty * 2 + i;
        float2 v0, v1;
        memcpy(&v0, &acc2[i][0], 8);
        memcpy(&v1, &acc2[i][1], 8);
        float4 o;
        o.x = v0.x * SCALE;
        o.y = v0.y * SCALE;
        o.z = v1.x * SCALE;
        o.w = v1.y * SCALE;
        *(float4*)&out[(size_t)r * HH + tx * 4] = o;
    }
}

// ---------------------------------------------------------------------------
// Launch
// ---------------------------------------------------------------------------
extern "C" void kernel_launch(void* const* d_in, const int* in_sizes, int n_in,
                              void* d_out, int out_size)
{
    const float* idx = (const float*)d_in[0];
    const float* Wq  = (const float*)d_in[1];
    const float* bq  = (const float*)d_in[2];
    const float* Wk  = (const float*)d_in[3];
    const float* bk  = (const float*)d_in[4];
    const float* Wv  = (const float*)d_in[5];
    const float* bv  = (const float*)d_in[6];
    float* out = (float*)d_out;

    prep_kernel<<<192, 256>>>(Wq, Wk, Wv);

    qkv_mma_kernel<<<BT / 64, 256, QKV_SMEM>>>(idx, bq, bk, bv);

    out_kernel<<<BT / 32, 256>>>(out);
}